// round 8
// baseline (speedup 1.0000x reference)
#include <cuda_runtime.h>
#include <math.h>

#define B_   16
#define C_   384
#define CH_  64
#define CF_  193
#define KP_  256     // padded K dim for irfft tables
#define HW_  16384   // 128*128
#define POOLB (B_ * C_)   // 6144

__device__ float g_y0[B_ * C_];          // pooled means
__device__ float g_W1c [CH_ * C_];       // W1 center taps   [j][n]
__device__ float g_W2cT[CH_ * C_];       // W2 center taps^T [j][c]
__device__ float g_dftSC[CF_ * C_];      // fwd DFT cos [k][n]
__device__ float g_dftSS[CF_ * C_];      // fwd DFT sin [k][n]
__device__ float g_dftIC[C_ * KP_];      // irfft cos*wgt [n][k], 0-padded k>=193
__device__ float g_dftIS[C_ * KP_];      // irfft sin*wgt [n][k], 0-padded

// ---------------------------------------------------------------------------
// Kernel 1: global average pool (blocks 0..6143, clean hot path) + 96
// appended side blocks: weight compaction (12) + DFT table build (84).
// ---------------------------------------------------------------------------
__global__ __launch_bounds__(256) void pool_kernel(
    const float* __restrict__ x,
    const float* __restrict__ W1, const float* __restrict__ W2)
{
    const int bid = blockIdx.x;
    const int t   = threadIdx.x;

    if (bid >= POOLB) {
        const int s = bid - POOLB;                      // 0..95
        if (s < 6) {                                    // W1 center taps
            for (int e = s * 4096 + t; e < (s + 1) * 4096; e += 256) {
                int j = e / C_, n = e - j * C_;
                g_W1c[e] = W1[j * (C_ * 9) + n * 9 + 4];
            }
        } else if (s < 12) {                            // W2 center taps ^T
            for (int e = (s - 6) * 4096 + t; e < (s - 5) * 4096; e += 256) {
                int j = e / C_, c = e - j * C_;
                g_W2cT[e] = W2[c * (CH_ * 9) + j * 9 + 4];
            }
        } else {
            __shared__ float cT[C_], sT[C_];
            for (int m = t; m < C_; m += 256) {
                float sv, cv;
                sincosf((float)m * (6.283185307179586f / (float)C_), &sv, &cv);
                cT[m] = cv;
                sT[m] = sv;
            }
            __syncthreads();
            if (s < 54) {                               // forward [k][n]
                const int g = s - 12;                   // 0..41
                const int NT = CF_ * C_;
                const int lo = (NT * g) / 42, hi = (NT * (g + 1)) / 42;
                for (int e = lo + t; e < hi; e += 256) {
                    int k = e / C_, n = e - k * C_;
                    int m = (k * n) % C_;
                    g_dftSC[e] = cT[m];
                    g_dftSS[e] = sT[m];
                }
            } else {                                    // inverse [n][KP], wgt folded
                const int g = s - 54;                   // 0..41
                const int NT = C_ * KP_;
                const int lo = (NT * g) / 42, hi = (NT * (g + 1)) / 42;
                for (int e = lo + t; e < hi; e += 256) {
                    int n = e / KP_, k = e - n * KP_;
                    if (k >= CF_) { g_dftIC[e] = 0.f; g_dftIS[e] = 0.f; continue; }
                    int m = (k * n) % C_;
                    float wgt = (k >= 1 && k <= 191) ? 2.f : 1.f;
                    g_dftIC[e] = wgt * cT[m];
                    g_dftIS[e] = wgt * sT[m];
                }
            }
        }
        return;
    }

    const float4* __restrict__ p =
        reinterpret_cast<const float4*>(x + (size_t)bid * HW_);
    float s = 0.f;
#pragma unroll
    for (int i = 0; i < 16; ++i) {
        float4 v = __ldcs(p + t + 256 * i);
        s += (v.x + v.y) + (v.z + v.w);
    }
#pragma unroll
    for (int o = 16; o > 0; o >>= 1) s += __shfl_down_sync(0xffffffffu, s, o);
    __shared__ float ws[8];
    if ((t & 31) == 0) ws[t >> 5] = s;
    __syncthreads();
    if (t < 8) {
        s = ws[t];
#pragma unroll
        for (int o = 4; o > 0; o >>= 1) s += __shfl_down_sync(0xffu, s, o);
        if (t == 0) g_y0[bid] = s * (1.f / (float)HW_);
    }
}

// ---------------------------------------------------------------------------
// Kernel 2: the entire tail, one block per batch (16 x 1024 threads).
//   phase h   : warp per j (2 rounds)        -> hs[64]
//   phase y   : thread per c                 -> ys[384]
//   phase spec: warp per bin k (7 rounds)    -> sRe/sIm[256] (padded)
//   phase ifft: warp per output n (12 rounds)-> out
// All big operands (Ws1/Ws2, DFT tables) stream from L2 (deduped across the
// 16 concurrent blocks).
// ---------------------------------------------------------------------------
__global__ __launch_bounds__(1024) void k_tail(
    const float* __restrict__ b1, const float* __restrict__ b2,
    const float* __restrict__ Ws1, const float* __restrict__ bs1,
    const float* __restrict__ Ws2, const float* __restrict__ bs2,
    float* __restrict__ out)
{
    const int b    = blockIdx.x;
    const int t    = threadIdx.x;       // 0..1023
    const int w    = t >> 5;            // 0..31
    const int lane = t & 31;

    __shared__ __align__(16) float y0s[C_];
    __shared__ __align__(16) float ys [C_];
    __shared__ __align__(16) float sRe[KP_];
    __shared__ __align__(16) float sIm[KP_];
    __shared__ float hs[CH_];

    if (t < C_)  y0s[t] = g_y0[b * C_ + t];
    if (t < KP_) { sRe[t] = 0.f; sIm[t] = 0.f; }
    __syncthreads();

    // ---- h[j] = relu(y0 . W1c[j,:] + b1[j]) : warp per j, 2 rounds ----
    const float4* __restrict__ y04 = reinterpret_cast<const float4*>(y0s);
#pragma unroll
    for (int r = 0; r < 2; ++r) {
        const int j = w + 32 * r;
        const float4* __restrict__ wr = reinterpret_cast<const float4*>(g_W1c + j * C_);
        float acc = 0.f;
#pragma unroll
        for (int i = 0; i < 3; ++i) {
            float4 a = y04[lane * 3 + i];
            float4 ww = wr[lane * 3 + i];
            acc += a.x * ww.x + a.y * ww.y + a.z * ww.z + a.w * ww.w;
        }
#pragma unroll
        for (int o = 16; o > 0; o >>= 1) acc += __shfl_down_sync(0xffffffffu, acc, o);
        if (lane == 0) hs[j] = fmaxf(acc + b1[j], 0.f);
    }
    __syncthreads();

    // ---- y[c] = sigmoid(h . W2cT[:,c] + b2[c]) : thread per c ----
    if (t < C_) {
        float acc = b2[t];
#pragma unroll
        for (int j = 0; j < CH_; ++j)
            acc += hs[j] * g_W2cT[j * C_ + t];
        ys[t] = 1.f / (1.f + expf(-acc));
    }
    __syncthreads();

    // ---- spec: warp per bin k, 7 rounds ----
    const float4* __restrict__ yv4 = reinterpret_cast<const float4*>(ys);
    for (int k = w; k < CF_; k += 32) {
        const float4* __restrict__ tc = reinterpret_cast<const float4*>(g_dftSC + k * C_);
        const float4* __restrict__ tsn = reinterpret_cast<const float4*>(g_dftSS + k * C_);
        const float4* __restrict__ u4 = reinterpret_cast<const float4*>(Ws1 + k * C_);
        const float4* __restrict__ v4 = reinterpret_cast<const float4*>(Ws2 + k * C_);
        float re = 0.f, im = 0.f, a1 = 0.f, a2 = 0.f;
#pragma unroll
        for (int i = 0; i < 3; ++i) {
            const int q = lane * 3 + i;
            float4 y = yv4[q];
            float4 c = tc[q], s = tsn[q], u = u4[q], v = v4[q];
            re += y.x * c.x + y.y * c.y + y.z * c.z + y.w * c.w;
            im -= y.x * s.x + y.y * s.y + y.z * s.z + y.w * s.w;
            a1 += y.x * u.x + y.y * u.y + y.z * u.z + y.w * u.w;
            a2 += y.x * v.x + y.y * v.y + y.z * v.z + y.w * v.w;
        }
#pragma unroll
        for (int o = 16; o > 0; o >>= 1) {
            re += __shfl_down_sync(0xffffffffu, re, o);
            im += __shfl_down_sync(0xffffffffu, im, o);
            a1 += __shfl_down_sync(0xffffffffu, a1, o);
            a2 += __shfl_down_sync(0xffffffffu, a2, o);
        }
        if (lane == 0) {
            float s1  = fmaxf(a1 + bs1[k], 0.f);
            float s2  = fmaxf(a2 + bs2[k], 0.f);
            float amp = sqrtf(re * re + im * im) * s1;
            float ph  = atan2f(im, re) * s2;
            float sp, cp;
            sincosf(ph, &sp, &cp);
            sRe[k] = amp * cp;
            sIm[k] = amp * sp;
        }
    }
    __syncthreads();

    // ---- irfft + gate: warp per output n, 12 rounds ----
    const float4* __restrict__ re4 = reinterpret_cast<const float4*>(sRe);
    const float4* __restrict__ im4 = reinterpret_cast<const float4*>(sIm);
#pragma unroll
    for (int r = 0; r < 12; ++r) {
        const int n = w + 32 * r;
        const float4* __restrict__ tc = reinterpret_cast<const float4*>(g_dftIC + n * KP_);
        const float4* __restrict__ tsn = reinterpret_cast<const float4*>(g_dftIS + n * KP_);
        float acc = 0.f;
#pragma unroll
        for (int i = 0; i < 2; ++i) {
            const int q = lane * 2 + i;
            float4 c = tc[q], s = tsn[q], rr = re4[q], mm = im4[q];
            acc += c.x * rr.x + c.y * rr.y + c.z * rr.z + c.w * rr.w;
            acc -= s.x * mm.x + s.y * mm.y + s.z * mm.z + s.w * mm.w;
        }
#pragma unroll
        for (int o = 16; o > 0; o >>= 1) acc += __shfl_down_sync(0xffffffffu, acc, o);
        if (lane == 0) {
            float xr = acc * (1.f / (float)C_);
            out[b * C_ + n] = xr * ys[n];
        }
    }
}

// ---------------------------------------------------------------------------
extern "C" void kernel_launch(void* const* d_in, const int* in_sizes, int n_in,
                              void* d_out, int out_size) {
    const float* x   = (const float*)d_in[0];
    const float* W1  = (const float*)d_in[1];
    const float* b1  = (const float*)d_in[2];
    const float* W2  = (const float*)d_in[3];
    const float* b2  = (const float*)d_in[4];
    const float* Ws1 = (const float*)d_in[5];
    const float* bs1 = (const float*)d_in[6];
    const float* Ws2 = (const float*)d_in[7];
    const float* bs2 = (const float*)d_in[8];
    float* out = (float*)d_out;

    pool_kernel<<<POOLB + 96, 256>>>(x, W1, W2);
    k_tail<<<B_, 1024>>>(b1, b2, Ws1, bs1, Ws2, bs2, out);
}

// round 9
// speedup vs baseline: 1.0963x; 1.0963x over previous
#include <cuda_runtime.h>
#include <math.h>

#define B_   16
#define C_   384
#define CH_  64
#define CF_  193
#define KP_  256     // padded K dim for irfft tables
#define HW_  16384   // 128*128
#define POOLB (B_ * C_)   // 6144

__device__ float g_y0[B_ * C_];          // pooled means
__device__ float g_ys[B_ * C_];          // sigmoid gate y
__device__ float g_rRe[B_ * CF_];        // spectral re
__device__ float g_rIm[B_ * CF_];        // spectral im
__device__ float g_W1c [CH_ * C_];       // W1 center taps   [j][n]
__device__ float g_W2cT[CH_ * C_];       // W2 center taps^T [j][c]
__device__ float g_dftSC[CF_ * C_];      // fwd DFT cos [k][n]
__device__ float g_dftSS[CF_ * C_];      // fwd DFT sin [k][n]
__device__ float g_dftIC[C_ * KP_];      // irfft cos*wgt [n][k], 0-padded
__device__ float g_dftIS[C_ * KP_];      // irfft sin*wgt [n][k], 0-padded

// tail-chain counters (zero-init; self-reset at end of every call)
__device__ int g_y_done[B_];
__device__ int g_c_spec[B_];
__device__ int g_c_fin;

// ---------------------------------------------------------------------------
// Kernel 1: global average pool (blocks 0..6143) + 96 side blocks:
// weight compaction (12) + DFT table build (84). (R6-proven, ~56us)
// ---------------------------------------------------------------------------
__global__ __launch_bounds__(256) void pool_kernel(
    const float* __restrict__ x,
    const float* __restrict__ W1, const float* __restrict__ W2)
{
    const int bid = blockIdx.x;
    const int t   = threadIdx.x;

    if (bid >= POOLB) {
        const int s = bid - POOLB;                      // 0..95
        if (s < 6) {
            for (int e = s * 4096 + t; e < (s + 1) * 4096; e += 256) {
                int j = e / C_, n = e - j * C_;
                g_W1c[e] = W1[j * (C_ * 9) + n * 9 + 4];
            }
        } else if (s < 12) {
            for (int e = (s - 6) * 4096 + t; e < (s - 5) * 4096; e += 256) {
                int j = e / C_, c = e - j * C_;
                g_W2cT[e] = W2[c * (CH_ * 9) + j * 9 + 4];
            }
        } else {
            __shared__ float cT[C_], sT[C_];
            for (int m = t; m < C_; m += 256) {
                float sv, cv;
                sincosf((float)m * (6.283185307179586f / (float)C_), &sv, &cv);
                cT[m] = cv;
                sT[m] = sv;
            }
            __syncthreads();
            if (s < 54) {                               // forward [k][n]
                const int g = s - 12;
                const int NT = CF_ * C_;
                const int lo = (NT * g) / 42, hi = (NT * (g + 1)) / 42;
                for (int e = lo + t; e < hi; e += 256) {
                    int k = e / C_, n = e - k * C_;
                    int m = (k * n) % C_;
                    g_dftSC[e] = cT[m];
                    g_dftSS[e] = sT[m];
                }
            } else {                                    // inverse [n][KP]
                const int g = s - 54;
                const int NT = C_ * KP_;
                const int lo = (NT * g) / 42, hi = (NT * (g + 1)) / 42;
                for (int e = lo + t; e < hi; e += 256) {
                    int n = e / KP_, k = e - n * KP_;
                    if (k >= CF_) { g_dftIC[e] = 0.f; g_dftIS[e] = 0.f; continue; }
                    int m = (k * n) % C_;
                    float wgt = (k >= 1 && k <= 191) ? 2.f : 1.f;
                    g_dftIC[e] = wgt * cT[m];
                    g_dftIS[e] = wgt * sT[m];
                }
            }
        }
        return;
    }

    const float4* __restrict__ p =
        reinterpret_cast<const float4*>(x + (size_t)bid * HW_);
    float s = 0.f;
#pragma unroll
    for (int i = 0; i < 16; ++i) {
        float4 v = __ldcs(p + t + 256 * i);
        s += (v.x + v.y) + (v.z + v.w);
    }
#pragma unroll
    for (int o = 16; o > 0; o >>= 1) s += __shfl_down_sync(0xffffffffu, s, o);
    __shared__ float ws[8];
    if ((t & 31) == 0) ws[t >> 5] = s;
    __syncthreads();
    if (t < 8) {
        s = ws[t];
#pragma unroll
        for (int o = 4; o > 0; o >>= 1) s += __shfl_down_sync(0xffu, s, o);
        if (t == 0) g_y0[bid] = s * (1.f / (float)HW_);
    }
}

// ---------------------------------------------------------------------------
// Kernel 2: fused tail, 1184 blocks x 256 threads, internal spin-chain.
//   [0..15]      y blocks   : h -> y per batch            -> g_ys, y_done[b]
//   [16..415]    spec blocks: 8 bins each, spin y_done[b] -> g_rRe/Im, c_spec
//   [416..1183]  irfft blocks: 8 outs each, spin c_spec[b]==25 -> out
// Waiters have strictly higher block indices than their producers
// (index-ordered dispatch => no deadlock). Counters self-reset at the end.
// ---------------------------------------------------------------------------
__global__ __launch_bounds__(256) void k_tail(
    const float* __restrict__ b1, const float* __restrict__ b2,
    const float* __restrict__ Ws1, const float* __restrict__ bs1,
    const float* __restrict__ Ws2, const float* __restrict__ bs2,
    float* __restrict__ out)
{
    const int bid  = blockIdx.x;
    const int t    = threadIdx.x;
    const int w    = t >> 5;
    const int lane = t & 31;

    if (bid < B_) {
        // ---------------- y block: h then y for batch bid ----------------
        const int b = bid;
        __shared__ __align__(16) float y0s[C_];
        __shared__ float hs[CH_];
        for (int m = t; m < C_; m += 256) y0s[m] = g_y0[b * C_ + m];
        __syncthreads();

        const float4* __restrict__ y04 = reinterpret_cast<const float4*>(y0s);
#pragma unroll
        for (int r = 0; r < 8; ++r) {
            const int j = w + 8 * r;
            const float4* __restrict__ wr =
                reinterpret_cast<const float4*>(g_W1c + j * C_);
            float acc = 0.f;
#pragma unroll
            for (int i = 0; i < 3; ++i) {
                float4 a = y04[lane * 3 + i];
                float4 ww = wr[lane * 3 + i];
                acc += a.x * ww.x + a.y * ww.y + a.z * ww.z + a.w * ww.w;
            }
#pragma unroll
            for (int o = 16; o > 0; o >>= 1)
                acc += __shfl_down_sync(0xffffffffu, acc, o);
            if (lane == 0) hs[j] = fmaxf(acc + b1[j], 0.f);
        }
        __syncthreads();

        for (int c = t; c < C_; c += 256) {
            float acc = b2[c];
#pragma unroll
            for (int j = 0; j < CH_; ++j)
                acc += hs[j] * g_W2cT[j * C_ + c];
            g_ys[b * C_ + c] = 1.f / (1.f + expf(-acc));
        }
        __syncthreads();
        if (t == 0) {
            __threadfence();
            atomicExch(&g_y_done[b], 1);
        }
        return;
    }

    if (bid < 16 + 400) {
        // ---------------- spec block: 8 bins of batch b ----------------
        const int s  = bid - 16;
        const int b  = s / 25;
        const int kg = s - b * 25;

        if (t == 0) {
            while (atomicAdd(&g_y_done[b], 0) == 0) __nanosleep(64);
            __threadfence();
        }
        __syncthreads();

        __shared__ __align__(16) float ys[C_];
        for (int m = t; m < C_; m += 256) ys[m] = g_ys[b * C_ + m];
        __syncthreads();

        const int k = kg * 8 + w;
        if (k < CF_) {
            const float4* __restrict__ tc = reinterpret_cast<const float4*>(g_dftSC + k * C_);
            const float4* __restrict__ tn = reinterpret_cast<const float4*>(g_dftSS + k * C_);
            const float4* __restrict__ u4 = reinterpret_cast<const float4*>(Ws1 + k * C_);
            const float4* __restrict__ v4 = reinterpret_cast<const float4*>(Ws2 + k * C_);
            const float4* __restrict__ yv4 = reinterpret_cast<const float4*>(ys);
            float re = 0.f, im = 0.f, a1 = 0.f, a2 = 0.f;
#pragma unroll
            for (int i = 0; i < 3; ++i) {
                const int q = lane * 3 + i;
                float4 y = yv4[q];
                float4 c = tc[q], sn = tn[q], u = u4[q], v = v4[q];
                re += y.x * c.x + y.y * c.y + y.z * c.z + y.w * c.w;
                im -= y.x * sn.x + y.y * sn.y + y.z * sn.z + y.w * sn.w;
                a1 += y.x * u.x + y.y * u.y + y.z * u.z + y.w * u.w;
                a2 += y.x * v.x + y.y * v.y + y.z * v.z + y.w * v.w;
            }
#pragma unroll
            for (int o = 16; o > 0; o >>= 1) {
                re += __shfl_down_sync(0xffffffffu, re, o);
                im += __shfl_down_sync(0xffffffffu, im, o);
                a1 += __shfl_down_sync(0xffffffffu, a1, o);
                a2 += __shfl_down_sync(0xffffffffu, a2, o);
            }
            if (lane == 0) {
                float s1  = fmaxf(a1 + bs1[k], 0.f);
                float s2  = fmaxf(a2 + bs2[k], 0.f);
                float amp = sqrtf(re * re + im * im) * s1;
                float ph  = atan2f(im, re) * s2;
                float sp, cp;
                sincosf(ph, &sp, &cp);
                g_rRe[b * CF_ + k] = amp * cp;
                g_rIm[b * CF_ + k] = amp * sp;
            }
        }
        __syncthreads();
        if (t == 0) {
            __threadfence();
            atomicAdd(&g_c_spec[b], 1);
        }
        return;
    }

    // ---------------- irfft block: 8 outputs of batch b ----------------
    {
        const int s  = bid - 416;
        const int b  = s / 48;
        const int ng = s - b * 48;

        if (t == 0) {
            while (atomicAdd(&g_c_spec[b], 0) < 25) __nanosleep(64);
            __threadfence();
        }
        __syncthreads();

        __shared__ __align__(16) float sRe[KP_], sIm[KP_];
        for (int m = t; m < KP_; m += 256) {
            sRe[m] = (m < CF_) ? g_rRe[b * CF_ + m] : 0.f;
            sIm[m] = (m < CF_) ? g_rIm[b * CF_ + m] : 0.f;
        }
        __syncthreads();

        const int n = ng * 8 + w;
        const float4* __restrict__ tc = reinterpret_cast<const float4*>(g_dftIC + n * KP_);
        const float4* __restrict__ tn = reinterpret_cast<const float4*>(g_dftIS + n * KP_);
        const float4* __restrict__ re4 = reinterpret_cast<const float4*>(sRe);
        const float4* __restrict__ im4 = reinterpret_cast<const float4*>(sIm);

        float acc = 0.f;
#pragma unroll
        for (int i = 0; i < 2; ++i) {
            const int q = lane * 2 + i;
            float4 c = tc[q], sn = tn[q], rr = re4[q], mm = im4[q];
            acc += c.x * rr.x + c.y * rr.y + c.z * rr.z + c.w * rr.w;
            acc -= sn.x * mm.x + sn.y * mm.y + sn.z * mm.z + sn.w * mm.w;
        }
#pragma unroll
        for (int o = 16; o > 0; o >>= 1) acc += __shfl_down_sync(0xffffffffu, acc, o);
        if (lane == 0) {
            float xr = acc * (1.f / (float)C_);
            out[b * C_ + n] = xr * g_ys[b * C_ + n];
        }
        __syncthreads();
        if (t == 0) {
            int old = atomicAdd(&g_c_fin, 1);
            if (old == 767) {               // last irfft block: reset all state
#pragma unroll
                for (int i = 0; i < B_; ++i) {
                    g_y_done[i] = 0;
                    g_c_spec[i] = 0;
                }
                g_c_fin = 0;
                __threadfence();
            }
        }
    }
}

// ---------------------------------------------------------------------------
extern "C" void kernel_launch(void* const* d_in, const int* in_sizes, int n_in,
                              void* d_out, int out_size) {
    const float* x   = (const float*)d_in[0];
    const float* W1  = (const float*)d_in[1];
    const float* b1  = (const float*)d_in[2];
    const float* W2  = (const float*)d_in[3];
    const float* b2  = (const float*)d_in[4];
    const float* Ws1 = (const float*)d_in[5];
    const float* bs1 = (const float*)d_in[6];
    const float* Ws2 = (const float*)d_in[7];
    const float* bs2 = (const float*)d_in[8];
    float* out = (float*)d_out;

    pool_kernel<<<POOLB + 96, 256>>>(x, W1, W2);
    k_tail<<<16 + 400 + 768, 256>>>(b1, b2, Ws1, bs1, Ws2, bs2, out);
}

// round 10
// speedup vs baseline: 1.1876x; 1.0832x over previous
#include <cuda_runtime.h>
#include <math.h>

#define B_   16
#define C_   384
#define CH_  64
#define CF_  193
#define KP_  256     // padded K dim for irfft tables
#define HW_  16384   // 128*128
#define POOLB (B_ * C_)   // 6144
#define SIDEB 104         // 12 weights + 84 tables + 8 Ws prefetch

__device__ float g_y0[B_ * C_];          // pooled means
__device__ float g_ys[B_ * C_];          // sigmoid gate y
__device__ float g_rRe[B_ * CF_];        // spectral re
__device__ float g_rIm[B_ * CF_];        // spectral im
__device__ float g_W1c [CH_ * C_];       // W1 center taps   [j][n]
__device__ float g_W2cT[CH_ * C_];       // W2 center taps^T [j][c]
__device__ float g_dftSC[CF_ * C_];      // fwd DFT cos [k][n]
__device__ float g_dftSS[CF_ * C_];      // fwd DFT sin [k][n]
__device__ float g_dftIC[C_ * KP_];      // irfft cos*wgt [n][k], 0-padded
__device__ float g_dftIS[C_ * KP_];      // irfft sin*wgt [n][k], 0-padded
__device__ float g_sink[16];             // prefetch sink (never read)

// ---------------------------------------------------------------------------
// Kernel 1: global average pool (blocks 0..6143) + side blocks:
// weight compaction (12), DFT tables (84), Ws1/Ws2 L2 prefetch (8).
// ---------------------------------------------------------------------------
__global__ __launch_bounds__(256) void pool_kernel(
    const float* __restrict__ x,
    const float* __restrict__ W1, const float* __restrict__ W2,
    const float* __restrict__ Ws1, const float* __restrict__ Ws2)
{
    const int bid = blockIdx.x;
    const int t   = threadIdx.x;

    if (bid >= POOLB) {
        const int s = bid - POOLB;                      // 0..103
        if (s < 6) {
            for (int e = s * 4096 + t; e < (s + 1) * 4096; e += 256) {
                int j = e / C_, n = e - j * C_;
                g_W1c[e] = W1[j * (C_ * 9) + n * 9 + 4];
            }
        } else if (s < 12) {
            for (int e = (s - 6) * 4096 + t; e < (s - 5) * 4096; e += 256) {
                int j = e / C_, c = e - j * C_;
                g_W2cT[e] = W2[c * (CH_ * 9) + j * 9 + 4];
            }
        } else if (s < 96) {
            __shared__ float cT[C_], sT[C_];
            for (int m = t; m < C_; m += 256) {
                float sv, cv;
                sincosf((float)m * (6.283185307179586f / (float)C_), &sv, &cv);
                cT[m] = cv;
                sT[m] = sv;
            }
            __syncthreads();
            if (s < 54) {                               // forward [k][n]
                const int g = s - 12;
                const int NT = CF_ * C_;
                const int lo = (NT * g) / 42, hi = (NT * (g + 1)) / 42;
                for (int e = lo + t; e < hi; e += 256) {
                    int k = e / C_, n = e - k * C_;
                    int m = (k * n) % C_;
                    g_dftSC[e] = cT[m];
                    g_dftSS[e] = sT[m];
                }
            } else {                                    // inverse [n][KP]
                const int g = s - 54;
                const int NT = C_ * KP_;
                const int lo = (NT * g) / 42, hi = (NT * (g + 1)) / 42;
                for (int e = lo + t; e < hi; e += 256) {
                    int n = e / KP_, k = e - n * KP_;
                    if (k >= CF_) { g_dftIC[e] = 0.f; g_dftIS[e] = 0.f; continue; }
                    int m = (k * n) % C_;
                    float wgt = (k >= 1 && k <= 191) ? 2.f : 1.f;
                    g_dftIC[e] = wgt * cT[m];
                    g_dftIS[e] = wgt * sT[m];
                }
            }
        } else {                                        // Ws1/Ws2 L2 prefetch
            const int g = s - 96;                       // 0..7
            const float* src = (g < 4) ? Ws1 : Ws2;
            const int NT = CF_ * C_;                    // 74112
            const int gg = g & 3;
            const int lo = (NT * gg) / 4, hi = (NT * (gg + 1)) / 4;
            float acc = 0.f;
            for (int e = lo + t; e < hi; e += 256) acc += __ldcg(src + e);
#pragma unroll
            for (int o = 16; o > 0; o >>= 1) acc += __shfl_down_sync(0xffffffffu, acc, o);
            if (t == 0 && acc == 1e38f) g_sink[s - 96] = acc;  // never true; keeps loads
        }
        return;
    }

    const float4* __restrict__ p =
        reinterpret_cast<const float4*>(x + (size_t)bid * HW_);
    float s = 0.f;
#pragma unroll
    for (int i = 0; i < 16; ++i) {
        float4 v = __ldcs(p + t + 256 * i);
        s += (v.x + v.y) + (v.z + v.w);
    }
#pragma unroll
    for (int o = 16; o > 0; o >>= 1) s += __shfl_down_sync(0xffffffffu, s, o);
    __shared__ float ws[8];
    if ((t & 31) == 0) ws[t >> 5] = s;
    __syncthreads();
    if (t < 8) {
        s = ws[t];
#pragma unroll
        for (int o = 4; o > 0; o >>= 1) s += __shfl_down_sync(0xffu, s, o);
        if (t == 0) g_y0[bid] = s * (1.f / (float)HW_);
    }
}

// ---------------------------------------------------------------------------
// Kernel 2: SE gate, one block per batch (16 x 384). Operands L2-resident.
// ---------------------------------------------------------------------------
__global__ __launch_bounds__(384) void k_hy(
    const float* __restrict__ b1, const float* __restrict__ b2)
{
    const int b    = blockIdx.x;
    const int t    = threadIdx.x;
    const int w    = t >> 5;            // 0..11
    const int lane = t & 31;

    __shared__ __align__(16) float y0s[C_];
    __shared__ float hs[CH_];

    y0s[t] = g_y0[b * C_ + t];
    __syncthreads();

    const float4* __restrict__ y04 = reinterpret_cast<const float4*>(y0s);
    for (int j = w; j < CH_; j += 12) {
        const float4* __restrict__ wr = reinterpret_cast<const float4*>(g_W1c + j * C_);
        float acc = 0.f;
#pragma unroll
        for (int i = 0; i < 3; ++i) {
            float4 a = y04[lane * 3 + i];
            float4 ww = wr[lane * 3 + i];
            acc += a.x * ww.x + a.y * ww.y + a.z * ww.z + a.w * ww.w;
        }
#pragma unroll
        for (int o = 16; o > 0; o >>= 1) acc += __shfl_down_sync(0xffffffffu, acc, o);
        if (lane == 0) hs[j] = fmaxf(acc + b1[j], 0.f);
    }
    __syncthreads();

    {
        float acc = b2[t];
#pragma unroll
        for (int j = 0; j < CH_; ++j)
            acc += hs[j] * g_W2cT[j * C_ + t];
        g_ys[b * C_ + t] = 1.f / (1.f + expf(-acc));
    }
}

// ---------------------------------------------------------------------------
// Kernel 3: spectral bins. Block = (b, 8 bins) x 512 thr; TWO warps per bin
// (each owns half of n); combine via shared float atomics; 8-thread epilogue.
// ---------------------------------------------------------------------------
__global__ __launch_bounds__(512) void k_spec(
    const float* __restrict__ Ws1, const float* __restrict__ bs1,
    const float* __restrict__ Ws2, const float* __restrict__ bs2)
{
    const int b    = blockIdx.x / 25;
    const int kg   = blockIdx.x - b * 25;
    const int t    = threadIdx.x;
    const int w    = t >> 5;            // 0..15
    const int lane = t & 31;

    __shared__ __align__(16) float ys[C_];
    __shared__ float sAcc[8][4];

    for (int m = t; m < C_; m += 512) ys[m] = g_ys[b * C_ + m];
    if (t < 32) sAcc[t >> 2][t & 3] = 0.f;
    __syncthreads();

    const int slot = w >> 1;            // 0..7
    const int half = w & 1;
    const int k    = kg * 8 + slot;

    if (k < CF_) {
        const float4* __restrict__ tc = reinterpret_cast<const float4*>(g_dftSC + k * C_);
        const float4* __restrict__ tn = reinterpret_cast<const float4*>(g_dftSS + k * C_);
        const float4* __restrict__ u4 = reinterpret_cast<const float4*>(Ws1 + k * C_);
        const float4* __restrict__ v4 = reinterpret_cast<const float4*>(Ws2 + k * C_);
        const float4* __restrict__ yv4 = reinterpret_cast<const float4*>(ys);
        float re = 0.f, im = 0.f, a1 = 0.f, a2 = 0.f;
#pragma unroll
        for (int i = 0; i < 2; ++i) {
            const int idx = lane + 32 * i;
            if (idx < 48) {
                const int q = half * 48 + idx;
                float4 y = yv4[q];
                float4 c = tc[q], sn = tn[q], u = u4[q], v = v4[q];
                re += y.x * c.x + y.y * c.y + y.z * c.z + y.w * c.w;
                im -= y.x * sn.x + y.y * sn.y + y.z * sn.z + y.w * sn.w;
                a1 += y.x * u.x + y.y * u.y + y.z * u.z + y.w * u.w;
                a2 += y.x * v.x + y.y * v.y + y.z * v.z + y.w * v.w;
            }
        }
#pragma unroll
        for (int o = 16; o > 0; o >>= 1) {
            re += __shfl_down_sync(0xffffffffu, re, o);
            im += __shfl_down_sync(0xffffffffu, im, o);
            a1 += __shfl_down_sync(0xffffffffu, a1, o);
            a2 += __shfl_down_sync(0xffffffffu, a2, o);
        }
        if (lane == 0) {
            atomicAdd(&sAcc[slot][0], re);
            atomicAdd(&sAcc[slot][1], im);
            atomicAdd(&sAcc[slot][2], a1);
            atomicAdd(&sAcc[slot][3], a2);
        }
    }
    __syncthreads();

    if (t < 8) {
        const int kk = kg * 8 + t;
        if (kk < CF_) {
            float re = sAcc[t][0], im = sAcc[t][1];
            float s1 = fmaxf(sAcc[t][2] + bs1[kk], 0.f);
            float s2 = fmaxf(sAcc[t][3] + bs2[kk], 0.f);
            float amp = sqrtf(re * re + im * im) * s1;
            float ph  = atan2f(im, re) * s2;
            float sp, cp;
            sincosf(ph, &sp, &cp);
            g_rRe[b * CF_ + kk] = amp * cp;
            g_rIm[b * CF_ + kk] = amp * sp;
        }
    }
}

// ---------------------------------------------------------------------------
// Kernel 4: irfft + gate. Block = (b, 8 outputs) x 512 thr; TWO warps per n
// (each owns half of padded k = one float4 per lane per stream).
// ---------------------------------------------------------------------------
__global__ __launch_bounds__(512) void k_irfft(float* __restrict__ out)
{
    const int b  = blockIdx.x / 48;
    const int ng = blockIdx.x - b * 48;
    const int t  = threadIdx.x;
    const int w  = t >> 5;              // 0..15
    const int lane = t & 31;

    __shared__ __align__(16) float sRe[KP_], sIm[KP_];
    __shared__ float sAcc[8];

    if (t < KP_) {
        sRe[t] = (t < CF_) ? g_rRe[b * CF_ + t] : 0.f;
        sIm[t] = (t < CF_) ? g_rIm[b * CF_ + t] : 0.f;
    }
    if (t < 8) sAcc[t] = 0.f;
    __syncthreads();

    const int slot = w >> 1;            // 0..7
    const int half = w & 1;
    const int n    = ng * 8 + slot;
    const int q    = half * 32 + lane;  // 0..63 float4 index

    const float4* __restrict__ tc = reinterpret_cast<const float4*>(g_dftIC + n * KP_);
    const float4* __restrict__ tn = reinterpret_cast<const float4*>(g_dftIS + n * KP_);
    const float4* __restrict__ re4 = reinterpret_cast<const float4*>(sRe);
    const float4* __restrict__ im4 = reinterpret_cast<const float4*>(sIm);

    float acc;
    {
        float4 c = tc[q], sn = tn[q], rr = re4[q], mm = im4[q];
        acc  = c.x * rr.x + c.y * rr.y + c.z * rr.z + c.w * rr.w;
        acc -= sn.x * mm.x + sn.y * mm.y + sn.z * mm.z + sn.w * mm.w;
    }
#pragma unroll
    for (int o = 16; o > 0; o >>= 1) acc += __shfl_down_sync(0xffffffffu, acc, o);
    if (lane == 0) atomicAdd(&sAcc[slot], acc);
    __syncthreads();

    if (t < 8) {
        const int nn = ng * 8 + t;
        float xr = sAcc[t] * (1.f / (float)C_);
        out[b * C_ + nn] = xr * g_ys[b * C_ + nn];
    }
}

// ---------------------------------------------------------------------------
extern "C" void kernel_launch(void* const* d_in, const int* in_sizes, int n_in,
                              void* d_out, int out_size) {
    const float* x   = (const float*)d_in[0];
    const float* W1  = (const float*)d_in[1];
    const float* b1  = (const float*)d_in[2];
    const float* W2  = (const float*)d_in[3];
    const float* b2  = (const float*)d_in[4];
    const float* Ws1 = (const float*)d_in[5];
    const float* bs1 = (const float*)d_in[6];
    const float* Ws2 = (const float*)d_in[7];
    const float* bs2 = (const float*)d_in[8];
    float* out = (float*)d_out;

    pool_kernel<<<POOLB + SIDEB, 256>>>(x, W1, W2, Ws1, Ws2);
    k_hy<<<B_, C_>>>(b1, b2);
    k_spec<<<B_ * 25, 512>>>(Ws1, bs1, Ws2, bs2);
    k_irfft<<<B_ * 48, 512>>>(out);
}

// round 11
// speedup vs baseline: 1.2207x; 1.0279x over previous
#include <cuda_runtime.h>
#include <math.h>

#define B_   16
#define C_   384
#define CH_  64
#define CF_  193
#define KP_  256     // padded K dim for irfft tables
#define HW_  16384   // 128*128
#define POOLB (B_ * C_)   // 6144
#define SIDEB 104         // 12 weights + 84 tables + 8 Ws prefetch
#define CLS  8            // cluster size (blocks per batch)

__device__ float g_y0[B_ * C_];          // pooled means
__device__ float g_rRe[B_ * CF_];        // spectral re
__device__ float g_rIm[B_ * CF_];        // spectral im
__device__ float g_W1c [CH_ * C_];       // W1 center taps   [j][n]
__device__ float g_W2cT[CH_ * C_];       // W2 center taps^T [j][c]
__device__ float g_dftSC[CF_ * C_];      // fwd DFT cos [k][n]
__device__ float g_dftSS[CF_ * C_];      // fwd DFT sin [k][n]
__device__ float g_dftIC[C_ * KP_];      // irfft cos*wgt [n][k], 0-padded
__device__ float g_dftIS[C_ * KP_];      // irfft sin*wgt [n][k], 0-padded
__device__ float g_sink[16];             // prefetch sink (never read)

// ---------------------------------------------------------------------------
// Kernel 1: global average pool (blocks 0..6143) + side blocks:
// weight compaction (12), DFT tables (84), Ws1/Ws2 L2 prefetch (8).
// ---------------------------------------------------------------------------
__global__ __launch_bounds__(256) void pool_kernel(
    const float* __restrict__ x,
    const float* __restrict__ W1, const float* __restrict__ W2,
    const float* __restrict__ Ws1, const float* __restrict__ Ws2)
{
    const int bid = blockIdx.x;
    const int t   = threadIdx.x;

    if (bid >= POOLB) {
        const int s = bid - POOLB;                      // 0..103
        if (s < 6) {
            for (int e = s * 4096 + t; e < (s + 1) * 4096; e += 256) {
                int j = e / C_, n = e - j * C_;
                g_W1c[e] = W1[j * (C_ * 9) + n * 9 + 4];
            }
        } else if (s < 12) {
            for (int e = (s - 6) * 4096 + t; e < (s - 5) * 4096; e += 256) {
                int j = e / C_, c = e - j * C_;
                g_W2cT[e] = W2[c * (CH_ * 9) + j * 9 + 4];
            }
        } else if (s < 96) {
            __shared__ float cT[C_], sT[C_];
            for (int m = t; m < C_; m += 256) {
                float sv, cv;
                sincosf((float)m * (6.283185307179586f / (float)C_), &sv, &cv);
                cT[m] = cv;
                sT[m] = sv;
            }
            __syncthreads();
            if (s < 54) {                               // forward [k][n]
                const int g = s - 12;
                const int NT = CF_ * C_;
                const int lo = (NT * g) / 42, hi = (NT * (g + 1)) / 42;
                for (int e = lo + t; e < hi; e += 256) {
                    int k = e / C_, n = e - k * C_;
                    int m = (k * n) % C_;
                    g_dftSC[e] = cT[m];
                    g_dftSS[e] = sT[m];
                }
            } else {                                    // inverse [n][KP]
                const int g = s - 54;
                const int NT = C_ * KP_;
                const int lo = (NT * g) / 42, hi = (NT * (g + 1)) / 42;
                for (int e = lo + t; e < hi; e += 256) {
                    int n = e / KP_, k = e - n * KP_;
                    if (k >= CF_) { g_dftIC[e] = 0.f; g_dftIS[e] = 0.f; continue; }
                    int m = (k * n) % C_;
                    float wgt = (k >= 1 && k <= 191) ? 2.f : 1.f;
                    g_dftIC[e] = wgt * cT[m];
                    g_dftIS[e] = wgt * sT[m];
                }
            }
        } else {                                        // Ws1/Ws2 L2 prefetch
            const int g = s - 96;                       // 0..7
            const float* src = (g < 4) ? Ws1 : Ws2;
            const int NT = CF_ * C_;
            const int gg = g & 3;
            const int lo = (NT * gg) / 4, hi = (NT * (gg + 1)) / 4;
            float acc = 0.f;
            for (int e = lo + t; e < hi; e += 256) acc += __ldcg(src + e);
#pragma unroll
            for (int o = 16; o > 0; o >>= 1) acc += __shfl_down_sync(0xffffffffu, acc, o);
            if (t == 0 && acc == 1e38f) g_sink[g] = acc;   // never true; keeps loads
        }
        return;
    }

    const float4* __restrict__ p =
        reinterpret_cast<const float4*>(x + (size_t)bid * HW_);
    float s = 0.f;
#pragma unroll
    for (int i = 0; i < 16; ++i) {
        float4 v = __ldcs(p + t + 256 * i);
        s += (v.x + v.y) + (v.z + v.w);
    }
#pragma unroll
    for (int o = 16; o > 0; o >>= 1) s += __shfl_down_sync(0xffffffffu, s, o);
    __shared__ float ws[8];
    if ((t & 31) == 0) ws[t >> 5] = s;
    __syncthreads();
    if (t < 8) {
        s = ws[t];
#pragma unroll
        for (int o = 4; o > 0; o >>= 1) s += __shfl_down_sync(0xffu, s, o);
        if (t == 0) g_y0[bid] = s * (1.f / (float)HW_);
    }
}

// ---------------------------------------------------------------------------
// Kernel 2: whole tail in one launch. 16 clusters of 8 blocks (128 x 512).
// Cluster = one batch:
//   phase 1: every rank computes h -> y in shared (redundant, L2-resident)
//   phase 2: rank r computes bins [25r, 25r+25) -> g_rRe/Im; fence
//   --- barrier.cluster ---
//   phase 3: each rank loads all bins to smem, computes outputs [48r, 48r+48)
// ---------------------------------------------------------------------------
__global__ __launch_bounds__(512) __cluster_dims__(CLS, 1, 1)
void k_tail(
    const float* __restrict__ b1, const float* __restrict__ b2,
    const float* __restrict__ Ws1, const float* __restrict__ bs1,
    const float* __restrict__ Ws2, const float* __restrict__ bs2,
    float* __restrict__ out)
{
    const int b    = blockIdx.x / CLS;
    const int rank = blockIdx.x - b * CLS;     // 0..7
    const int t    = threadIdx.x;              // 0..511
    const int w    = t >> 5;                   // 0..15
    const int lane = t & 31;

    __shared__ __align__(16) float y0s[C_];
    __shared__ __align__(16) float ys [C_];
    __shared__ __align__(16) float sRe[KP_];
    __shared__ __align__(16) float sIm[KP_];
    __shared__ float hs[CH_];

    if (t < C_) y0s[t] = g_y0[b * C_ + t];
    __syncthreads();

    // ---- phase 1a: h[j], warp per j (4 rounds) ----
    const float4* __restrict__ y04 = reinterpret_cast<const float4*>(y0s);
#pragma unroll
    for (int r = 0; r < 4; ++r) {
        const int j = w + 16 * r;
        const float4* __restrict__ wr = reinterpret_cast<const float4*>(g_W1c + j * C_);
        float acc = 0.f;
#pragma unroll
        for (int i = 0; i < 3; ++i) {
            float4 a = y04[lane * 3 + i];
            float4 ww = wr[lane * 3 + i];
            acc += a.x * ww.x + a.y * ww.y + a.z * ww.z + a.w * ww.w;
        }
#pragma unroll
        for (int o = 16; o > 0; o >>= 1) acc += __shfl_down_sync(0xffffffffu, acc, o);
        if (lane == 0) hs[j] = fmaxf(acc + b1[j], 0.f);
    }
    __syncthreads();

    // ---- phase 1b: y[c], thread per c ----
    if (t < C_) {
        float acc = b2[t];
#pragma unroll
        for (int j = 0; j < CH_; ++j)
            acc += hs[j] * g_W2cT[j * C_ + t];
        ys[t] = 1.f / (1.f + expf(-acc));
    }
    __syncthreads();

    // ---- phase 2: bins [25*rank, 25*rank+25), warp per bin ----
    {
        const int base = rank * 25;
        const int cnt  = (base + 25 <= CF_) ? 25 : (CF_ - base);  // rank7: 18
        const float4* __restrict__ yv4 = reinterpret_cast<const float4*>(ys);
        for (int kk = w; kk < cnt; kk += 16) {
            const int k = base + kk;
            const float4* __restrict__ tc = reinterpret_cast<const float4*>(g_dftSC + k * C_);
            const float4* __restrict__ tn = reinterpret_cast<const float4*>(g_dftSS + k * C_);
            const float4* __restrict__ u4 = reinterpret_cast<const float4*>(Ws1 + k * C_);
            const float4* __restrict__ v4 = reinterpret_cast<const float4*>(Ws2 + k * C_);
            float re = 0.f, im = 0.f, a1 = 0.f, a2 = 0.f;
#pragma unroll
            for (int i = 0; i < 3; ++i) {
                const int q = lane * 3 + i;
                float4 y = yv4[q];
                float4 c = tc[q], sn = tn[q], u = u4[q], v = v4[q];
                re += y.x * c.x + y.y * c.y + y.z * c.z + y.w * c.w;
                im -= y.x * sn.x + y.y * sn.y + y.z * sn.z + y.w * sn.w;
                a1 += y.x * u.x + y.y * u.y + y.z * u.z + y.w * u.w;
                a2 += y.x * v.x + y.y * v.y + y.z * v.z + y.w * v.w;
            }
#pragma unroll
            for (int o = 16; o > 0; o >>= 1) {
                re += __shfl_down_sync(0xffffffffu, re, o);
                im += __shfl_down_sync(0xffffffffu, im, o);
                a1 += __shfl_down_sync(0xffffffffu, a1, o);
                a2 += __shfl_down_sync(0xffffffffu, a2, o);
            }
            if (lane == 0) {
                float s1  = fmaxf(a1 + bs1[k], 0.f);
                float s2  = fmaxf(a2 + bs2[k], 0.f);
                float amp = sqrtf(re * re + im * im) * s1;
                float ph  = atan2f(im, re) * s2;
                float sp, cp;
                sincosf(ph, &sp, &cp);
                g_rRe[b * CF_ + k] = amp * cp;
                g_rIm[b * CF_ + k] = amp * sp;
            }
        }
    }

    // make bin writes visible cluster-wide, then cluster barrier
    __threadfence();
    asm volatile("barrier.cluster.arrive.aligned;" ::: "memory");
    asm volatile("barrier.cluster.wait.aligned;" ::: "memory");

    // ---- phase 3: irfft outputs [48*rank, 48*rank+48), warp per n ----
    if (t < KP_) {
        sRe[t] = (t < CF_) ? g_rRe[b * CF_ + t] : 0.f;
        sIm[t] = (t < CF_) ? g_rIm[b * CF_ + t] : 0.f;
    }
    __syncthreads();

    const float4* __restrict__ re4 = reinterpret_cast<const float4*>(sRe);
    const float4* __restrict__ im4 = reinterpret_cast<const float4*>(sIm);
#pragma unroll
    for (int r = 0; r < 3; ++r) {
        const int n = rank * 48 + w + 16 * r;
        const float4* __restrict__ tc = reinterpret_cast<const float4*>(g_dftIC + n * KP_);
        const float4* __restrict__ tn = reinterpret_cast<const float4*>(g_dftIS + n * KP_);
        float acc = 0.f;
#pragma unroll
        for (int i = 0; i < 2; ++i) {
            const int q = lane * 2 + i;
            float4 c = tc[q], sn = tn[q], rr = re4[q], mm = im4[q];
            acc += c.x * rr.x + c.y * rr.y + c.z * rr.z + c.w * rr.w;
            acc -= sn.x * mm.x + sn.y * mm.y + sn.z * mm.z + sn.w * mm.w;
        }
#pragma unroll
        for (int o = 16; o > 0; o >>= 1) acc += __shfl_down_sync(0xffffffffu, acc, o);
        if (lane == 0) {
            float xr = acc * (1.f / (float)C_);
            out[b * C_ + n] = xr * ys[n];
        }
    }
}

// ---------------------------------------------------------------------------
extern "C" void kernel_launch(void* const* d_in, const int* in_sizes, int n_in,
                              void* d_out, int out_size) {
    const float* x   = (const float*)d_in[0];
    const float* W1  = (const float*)d_in[1];
    const float* b1  = (const float*)d_in[2];
    const float* W2  = (const float*)d_in[3];
    const float* b2  = (const float*)d_in[4];
    const float* Ws1 = (const float*)d_in[5];
    const float* bs1 = (const float*)d_in[6];
    const float* Ws2 = (const float*)d_in[7];
    const float* bs2 = (const float*)d_in[8];
    float* out = (float*)d_out;

    pool_kernel<<<POOLB + SIDEB, 256>>>(x, W1, W2, Ws1, Ws2);
    k_tail<<<B_ * CLS, 512>>>(b1, b2, Ws1, bs1, Ws2, bs2, out);
}